// round 1
// baseline (speedup 1.0000x reference)
#include <cuda_runtime.h>
#include <cstdint>

#define TFRAMES 4
#define CFEAT   64
#define HIH     480
#define WIW     640
#define PPIX    (HIH*WIW)      // 307200
#define MAPW    256
#define HWCELLS 65536
#define MEMN    256
#define G3      768
#define AP      68             // smem pitch (float4-aligned, limits store conflicts to 4-way)

// ---------------- device scratch (static: no runtime allocation) ----------------
__device__ unsigned long long d_cellbest[HWCELLS];
__device__ float  d_hmap[HWCELLS];
__device__ unsigned char d_obs[HWCELLS];
__device__ float  d_state[HWCELLS*MEMN];   // 64 MB
__device__ float  d_tmph [HWCELLS*MEMN];   // 64 MB
__device__ float  d_xc   [HWCELLS*CFEAT];  // 16 MB
__device__ int    d_list_cell[HWCELLS];
__device__ int    d_list_pix [HWCELLS];
__device__ int    d_count;
__device__ int    d_maskmode;              // 0=int32, 1=uint8, 2=float32

// ---------------- helpers ----------------
__device__ __forceinline__ float lo32(unsigned long long v){ return __uint_as_float((unsigned)(v & 0xFFFFFFFFull)); }
__device__ __forceinline__ float hi32(unsigned long long v){ return __uint_as_float((unsigned)(v >> 32)); }

// ---------------- mask dtype detection (deterministic, data-driven) ----------------
__global__ void detect_mask_kernel(const unsigned char* __restrict__ mask)
{
    if (blockIdx.x != 0 || threadIdx.x != 0) return;
    bool big = false, off = false;
    for (int i = 0; i < 1024; ++i) {
        unsigned char b = mask[i];
        if (b > 1) big = true;
        if (b != 0 && (i & 3) != 0) off = true;
    }
    d_maskmode = big ? 2 : (off ? 1 : 0);
}

// ---------------- init (zero state / hmap / obs) ----------------
__global__ void init_all_kernel()
{
    int i = blockIdx.x * blockDim.x + threadIdx.x;
    int stride = gridDim.x * blockDim.x;
    float4 z = make_float4(0.f, 0.f, 0.f, 0.f);
    for (int j = i; j < HWCELLS*MEMN/4; j += stride) reinterpret_cast<float4*>(d_state)[j] = z;
    for (int j = i; j < HWCELLS; j += stride) { d_hmap[j] = 0.f; d_obs[j] = 0; }
}

__global__ void frame_reset_kernel()
{
    int i = blockIdx.x * blockDim.x + threadIdx.x;
    if (i < HWCELLS) d_cellbest[i] = 0ull;
    if (i == 0) d_count = 0;
}

// ---------------- per-pixel scatter: packed (ordered hv, ~pix) atomicMax ----------------
__global__ void scatter_kernel(const void* __restrict__ mask,
                               const int*  __restrict__ wtm,
                               const float* __restrict__ heights,
                               int t)
{
    int pix = blockIdx.x * blockDim.x + threadIdx.x;
    if (pix >= PPIX) return;
    long base = (long)t * PPIX + pix;
    int mm = d_maskmode;
    bool outlier;
    if (mm == 0)      outlier = ((const int*)mask)[base] != 0;
    else if (mm == 1) outlier = ((const unsigned char*)mask)[base] != 0;
    else              outlier = ((const float*)mask)[base] != 0.f;
    if (outlier) return;

    int wx = wtm[base*2 + 0];
    int wy = wtm[base*2 + 1];
    int idx = wy * MAPW + wx;

    float hv = heights[base] + 1000.0f;
    unsigned int bits = __float_as_uint(hv);
    unsigned int key  = (bits & 0x80000000u) ? ~bits : (bits | 0x80000000u);
    unsigned long long packed = ((unsigned long long)key << 32) | (unsigned int)(~(unsigned)pix);
    atomicMax(&d_cellbest[idx], packed);
}

// ---------------- per-cell: update height map / observed, compact updated cells ----------------
__global__ void cell_kernel()
{
    int i = blockIdx.x * blockDim.x + threadIdx.x;
    if (i >= HWCELLS) return;
    unsigned long long pb = d_cellbest[i];
    if (pb == 0ull) return;                     // no inlier pixel hit this cell
    unsigned int key = (unsigned int)(pb >> 32);
    unsigned int bits = (key & 0x80000000u) ? (key ^ 0x80000000u) : ~key;
    float cmax = __uint_as_float(bits);
    if (cmax > d_hmap[i]) {
        d_hmap[i] = cmax;
        d_obs[i]  = 1;
        int pix = (int)(~(unsigned int)(pb & 0xFFFFFFFFull));
        int pos = atomicAdd(&d_count, 1);
        d_list_cell[pos] = i;
        d_list_pix[pos]  = pix;
    }
}

// ---------------- gather winner-pixel features into compact X buffer ----------------
__global__ void gather_x_kernel(const float* __restrict__ features, int t)
{
    int c = threadIdx.x;                         // 64 threads
    int n = d_count;
    for (int pos = blockIdx.x; pos < n; pos += gridDim.x) {
        int pix = d_list_pix[pos];
        d_xc[pos*CFEAT + c] = features[((long)t*CFEAT + c)*PPIX + pix];
    }
}

// ---------------- fused GRU GEMM: 64 rows x 64 cols per block, f32x2 packed FMA ----------------
#define GRU_INNER(G0)                                                                  \
    _Pragma("unroll")                                                                  \
    for (int kk = 0; kk < 32; ++kk) {                                                  \
        float4 a4 = *reinterpret_cast<const float4*>(&sA[kk*AP + rb]);                 \
        unsigned long long ap0, ap1, ap2, ap3;                                         \
        asm("mov.b64 %0,{%1,%1};" : "=l"(ap0) : "f"(a4.x));                            \
        asm("mov.b64 %0,{%1,%1};" : "=l"(ap1) : "f"(a4.y));                            \
        asm("mov.b64 %0,{%1,%1};" : "=l"(ap2) : "f"(a4.z));                            \
        asm("mov.b64 %0,{%1,%1};" : "=l"(ap3) : "f"(a4.w));                            \
        _Pragma("unroll")                                                              \
        for (int g = 0; g < 3; ++g) {                                                  \
            float4 w4 = *reinterpret_cast<const float4*>(&sW[g][kk*AP + cb]);          \
            unsigned long long wp0, wp1;                                               \
            asm("mov.b64 %0,{%1,%2};" : "=l"(wp0) : "f"(w4.x), "f"(w4.y));             \
            asm("mov.b64 %0,{%1,%2};" : "=l"(wp1) : "f"(w4.z), "f"(w4.w));             \
            asm("fma.rn.f32x2 %0, %1, %2, %0;" : "+l"(acc[G0+g][0][0]) : "l"(ap0), "l"(wp0)); \
            asm("fma.rn.f32x2 %0, %1, %2, %0;" : "+l"(acc[G0+g][0][1]) : "l"(ap0), "l"(wp1)); \
            asm("fma.rn.f32x2 %0, %1, %2, %0;" : "+l"(acc[G0+g][1][0]) : "l"(ap1), "l"(wp0)); \
            asm("fma.rn.f32x2 %0, %1, %2, %0;" : "+l"(acc[G0+g][1][1]) : "l"(ap1), "l"(wp1)); \
            asm("fma.rn.f32x2 %0, %1, %2, %0;" : "+l"(acc[G0+g][2][0]) : "l"(ap2), "l"(wp0)); \
            asm("fma.rn.f32x2 %0, %1, %2, %0;" : "+l"(acc[G0+g][2][1]) : "l"(ap2), "l"(wp1)); \
            asm("fma.rn.f32x2 %0, %1, %2, %0;" : "+l"(acc[G0+g][3][0]) : "l"(ap3), "l"(wp0)); \
            asm("fma.rn.f32x2 %0, %1, %2, %0;" : "+l"(acc[G0+g][3][1]) : "l"(ap3), "l"(wp1)); \
        }                                                                              \
    }

__global__ __launch_bounds__(256) void gru_kernel(const float* __restrict__ Wih,
                                                  const float* __restrict__ Whh,
                                                  const float* __restrict__ bih,
                                                  const float* __restrict__ bhh)
{
    __shared__ float sA[32*AP];
    __shared__ float sW[3][32*AP];
    __shared__ int   sCell[64];

    int n = d_count;
    int row0 = blockIdx.x * 64;
    if (row0 >= n) return;
    int m0 = blockIdx.y * 64;

    int tid = threadIdx.x;
    int tx = tid & 15, ty = tid >> 4;
    int rb = ty * 4, cb = tx * 4;

    if (tid < 64) {
        int rr = min(row0 + tid, n - 1);
        sCell[tid] = d_list_cell[rr];
    }
    __syncthreads();

    // acc[gate 0..2 = x-part | 3..5 = h-part][row 0..3][colpair 0..1], packed f32x2
    unsigned long long acc[6][4][2];
#pragma unroll
    for (int g = 0; g < 6; ++g)
#pragma unroll
        for (int r = 0; r < 4; ++r) { acc[g][r][0] = 0ull; acc[g][r][1] = 0ull; }

    // ---- phase X: K = 64 over compact features ----
    for (int k0 = 0; k0 < CFEAT; k0 += 32) {
        for (int e = tid; e < 64*32; e += 256) {
            int r = e >> 5, kk = e & 31;
            int rr = min(row0 + r, n - 1);
            sA[kk*AP + r] = d_xc[rr*CFEAT + k0 + kk];
        }
        for (int e = tid; e < 3*64*32; e += 256) {
            int g = e >> 11, rem = e & 2047;
            int j = rem >> 5, kk = rem & 31;
            sW[g][kk*AP + j] = Wih[(g*256 + m0 + j)*CFEAT + k0 + kk];
        }
        __syncthreads();
        GRU_INNER(0)
        __syncthreads();
    }

    // ---- phase H: K = 256 over previous state ----
    for (int k0 = 0; k0 < MEMN; k0 += 32) {
        for (int e = tid; e < 64*32; e += 256) {
            int r = e >> 5, kk = e & 31;
            sA[kk*AP + r] = d_state[(long)sCell[r]*MEMN + k0 + kk];
        }
        for (int e = tid; e < 3*64*32; e += 256) {
            int g = e >> 11, rem = e & 2047;
            int j = rem >> 5, kk = rem & 31;
            sW[g][kk*AP + j] = Whh[(g*256 + m0 + j)*MEMN + k0 + kk];
        }
        __syncthreads();
        GRU_INNER(3)
        __syncthreads();
    }

    // ---- epilogue: biases + GRU gates + write new state to compact tmp buffer ----
    float bir[4], biz[4], bin_[4], bhr[4], bhz[4], bhn[4];
    {
        float4 v;
        v = *reinterpret_cast<const float4*>(&bih[      m0 + cb]); bir[0]=v.x; bir[1]=v.y; bir[2]=v.z; bir[3]=v.w;
        v = *reinterpret_cast<const float4*>(&bih[256 + m0 + cb]); biz[0]=v.x; biz[1]=v.y; biz[2]=v.z; biz[3]=v.w;
        v = *reinterpret_cast<const float4*>(&bih[512 + m0 + cb]); bin_[0]=v.x; bin_[1]=v.y; bin_[2]=v.z; bin_[3]=v.w;
        v = *reinterpret_cast<const float4*>(&bhh[      m0 + cb]); bhr[0]=v.x; bhr[1]=v.y; bhr[2]=v.z; bhr[3]=v.w;
        v = *reinterpret_cast<const float4*>(&bhh[256 + m0 + cb]); bhz[0]=v.x; bhz[1]=v.y; bhz[2]=v.z; bhz[3]=v.w;
        v = *reinterpret_cast<const float4*>(&bhh[512 + m0 + cb]); bhn[0]=v.x; bhn[1]=v.y; bhn[2]=v.z; bhn[3]=v.w;
    }

#pragma unroll
    for (int r = 0; r < 4; ++r) {
        int pos = row0 + rb + r;
        bool valid = pos < n;
        int cell = sCell[rb + r];
        float4 h4 = *reinterpret_cast<const float4*>(&d_state[(long)cell*MEMN + m0 + cb]);
        float ho[4] = {h4.x, h4.y, h4.z, h4.w};
        float hnew[4];
#pragma unroll
        for (int cc = 0; cc < 4; ++cc) {
            int cp = cc >> 1;
            float ir  = (cc & 1) ? hi32(acc[0][r][cp]) : lo32(acc[0][r][cp]);
            float iz  = (cc & 1) ? hi32(acc[1][r][cp]) : lo32(acc[1][r][cp]);
            float in_ = (cc & 1) ? hi32(acc[2][r][cp]) : lo32(acc[2][r][cp]);
            float hr  = (cc & 1) ? hi32(acc[3][r][cp]) : lo32(acc[3][r][cp]);
            float hz  = (cc & 1) ? hi32(acc[4][r][cp]) : lo32(acc[4][r][cp]);
            float hn  = (cc & 1) ? hi32(acc[5][r][cp]) : lo32(acc[5][r][cp]);
            ir += bir[cc]; iz += biz[cc]; in_ += bin_[cc];
            hr += bhr[cc]; hz += bhz[cc]; hn += bhn[cc];
            float rg = 1.f / (1.f + expf(-(ir + hr)));
            float zg = 1.f / (1.f + expf(-(iz + hz)));
            float ng = tanhf(in_ + rg * hn);
            hnew[cc] = (1.f - zg) * ng + zg * ho[cc];
        }
        if (valid) {
            float4 o; o.x = hnew[0]; o.y = hnew[1]; o.z = hnew[2]; o.w = hnew[3];
            *reinterpret_cast<float4*>(&d_tmph[(long)pos*MEMN + m0 + cb]) = o;
        }
    }
}

// ---------------- scatter new states back into the map ----------------
__global__ void scatter_h_kernel()
{
    int n = d_count;
    for (int pos = blockIdx.x; pos < n; pos += gridDim.x) {
        int cell = d_list_cell[pos];
        d_state[(long)cell*MEMN + threadIdx.x] = d_tmph[(long)pos*MEMN + threadIdx.x];
    }
}

// ---------------- outputs ----------------
__global__ void transpose_out_kernel(float* __restrict__ out, long out_size)
{
    __shared__ float tile[32][33];
    int c0 = blockIdx.x * 32;   // cell
    int m0 = blockIdx.y * 32;   // mem channel
    int tx = threadIdx.x, ty = threadIdx.y;
#pragma unroll
    for (int i = 0; i < 32; i += 8)
        tile[ty + i][tx] = d_state[(long)(c0 + ty + i)*MEMN + m0 + tx];
    __syncthreads();
#pragma unroll
    for (int i = 0; i < 32; i += 8) {
        long o = (long)(m0 + ty + i)*HWCELLS + c0 + tx;
        if (o < out_size) out[o] = tile[tx][ty + i];
    }
}

__global__ void tail_out_kernel(float* __restrict__ out, long out_size)
{
    int i = blockIdx.x * blockDim.x + threadIdx.x;
    if (i >= HWCELLS) return;
    long o1 = (long)MEMN*HWCELLS + i;
    long o2 = o1 + HWCELLS;
    if (o1 < out_size) out[o1] = d_obs[i] ? 1.f : 0.f;
    if (o2 < out_size) out[o2] = d_hmap[i];
}

// ---------------- launch ----------------
extern "C" void kernel_launch(void* const* d_in, const int* in_sizes, int n_in,
                              void* d_out, int out_size)
{
    // Resolve inputs by element count (robust to scalar inputs present or absent).
    const float* features = nullptr;
    const int*   wtm      = nullptr;
    const void*  mask     = nullptr;
    const float* heights  = nullptr;
    const float* Wih = nullptr; const float* Whh = nullptr;
    const float* bih = nullptr; const float* bhh = nullptr;

    for (int i = 0; i < n_in; ++i) {
        int s = in_sizes[i];
        if      (s == TFRAMES*CFEAT*PPIX) features = (const float*)d_in[i];
        else if (s == TFRAMES*PPIX*2)     wtm      = (const int*)d_in[i];
        else if (s == TFRAMES*PPIX)       { if (!mask) mask = d_in[i]; else heights = (const float*)d_in[i]; }
        else if (s == G3*CFEAT)           Wih = (const float*)d_in[i];
        else if (s == G3*MEMN)            Whh = (const float*)d_in[i];
        else if (s == G3)                 { if (!bih) bih = (const float*)d_in[i]; else bhh = (const float*)d_in[i]; }
    }
    float* out = (float*)d_out;

    detect_mask_kernel<<<1, 1>>>((const unsigned char*)mask);
    init_all_kernel<<<2048, 256>>>();

    for (int t = 0; t < TFRAMES; ++t) {
        frame_reset_kernel<<<(HWCELLS + 255)/256, 256>>>();
        scatter_kernel<<<(PPIX + 255)/256, 256>>>(mask, wtm, heights, t);
        cell_kernel<<<HWCELLS/256, 256>>>();
        gather_x_kernel<<<8192, 64>>>(features, t);
        gru_kernel<<<dim3(HWCELLS/64, 4), 256>>>(Wih, Whh, bih, bhh);
        scatter_h_kernel<<<8192, 256>>>();
    }

    transpose_out_kernel<<<dim3(HWCELLS/32, MEMN/32), dim3(32, 8)>>>(out, (long)out_size);
    tail_out_kernel<<<HWCELLS/256, 256>>>(out, (long)out_size);
}

// round 2
// speedup vs baseline: 1.0084x; 1.0084x over previous
#include <cuda_runtime.h>
#include <cstdint>

#define TFRAMES 4
#define CFEAT   64
#define HIH     480
#define WIW     640
#define PPIX    (HIH*WIW)      // 307200
#define MAPW    256
#define HWCELLS 65536
#define MEMN    256
#define G3      768
#define AP      68             // smem pitch (float4-aligned, limits store conflicts to 4-way)

// ---------------- device scratch (static: no runtime allocation) ----------------
__device__ unsigned long long d_cellbest[HWCELLS];
__device__ float  d_hmap[HWCELLS];
__device__ unsigned char d_obs[HWCELLS];
__device__ float  d_state[HWCELLS*MEMN];   // 64 MB
__device__ float  d_tmph [HWCELLS*MEMN];   // 64 MB
__device__ float  d_xc   [HWCELLS*CFEAT];  // 16 MB
__device__ int    d_list_cell[HWCELLS];
__device__ int    d_list_pix [HWCELLS];
__device__ int    d_count;
__device__ int    d_maskmode;              // 0=int32, 1=uint8, 2=float32

// ---------------- helpers ----------------
__device__ __forceinline__ float lo32(unsigned long long v){ return __uint_as_float((unsigned)(v & 0xFFFFFFFFull)); }
__device__ __forceinline__ float hi32(unsigned long long v){ return __uint_as_float((unsigned)(v >> 32)); }

// ---------------- mask dtype detection (deterministic, data-driven) ----------------
__global__ void detect_mask_kernel(const unsigned char* __restrict__ mask)
{
    if (blockIdx.x != 0 || threadIdx.x != 0) return;
    bool big = false, off = false;
    for (int i = 0; i < 1024; ++i) {
        unsigned char b = mask[i];
        if (b > 1) big = true;
        if (b != 0 && (i & 3) != 0) off = true;
    }
    d_maskmode = big ? 2 : (off ? 1 : 0);
}

// ---------------- init (zero state / hmap / obs) ----------------
__global__ void init_all_kernel()
{
    int i = blockIdx.x * blockDim.x + threadIdx.x;
    int stride = gridDim.x * blockDim.x;
    float4 z = make_float4(0.f, 0.f, 0.f, 0.f);
    for (int j = i; j < HWCELLS*MEMN/4; j += stride) reinterpret_cast<float4*>(d_state)[j] = z;
    for (int j = i; j < HWCELLS; j += stride) { d_hmap[j] = 0.f; d_obs[j] = 0; }
}

__global__ void frame_reset_kernel()
{
    int i = blockIdx.x * blockDim.x + threadIdx.x;
    if (i < HWCELLS) d_cellbest[i] = 0ull;
    if (i == 0) d_count = 0;
}

// ---------------- per-pixel scatter: packed (ordered hv, ~pix) atomicMax ----------------
__global__ void scatter_kernel(const void* __restrict__ mask,
                               const int*  __restrict__ wtm,
                               const float* __restrict__ heights,
                               int t)
{
    int pix = blockIdx.x * blockDim.x + threadIdx.x;
    if (pix >= PPIX) return;
    long base = (long)t * PPIX + pix;
    int mm = d_maskmode;
    bool outlier;
    if (mm == 0)      outlier = ((const int*)mask)[base] != 0;
    else if (mm == 1) outlier = ((const unsigned char*)mask)[base] != 0;
    else              outlier = ((const float*)mask)[base] != 0.f;
    if (outlier) return;

    int wx = wtm[base*2 + 0];
    int wy = wtm[base*2 + 1];
    int idx = wy * MAPW + wx;

    float hv = heights[base] + 1000.0f;
    unsigned int bits = __float_as_uint(hv);
    unsigned int key  = (bits & 0x80000000u) ? ~bits : (bits | 0x80000000u);
    unsigned long long packed = ((unsigned long long)key << 32) | (unsigned int)(~(unsigned)pix);
    atomicMax(&d_cellbest[idx], packed);
}

// ---------------- per-cell: update height map / observed, compact updated cells ----------------
__global__ void cell_kernel()
{
    int i = blockIdx.x * blockDim.x + threadIdx.x;
    if (i >= HWCELLS) return;
    unsigned long long pb = d_cellbest[i];
    if (pb == 0ull) return;                     // no inlier pixel hit this cell
    unsigned int key = (unsigned int)(pb >> 32);
    unsigned int bits = (key & 0x80000000u) ? (key ^ 0x80000000u) : ~key;
    float cmax = __uint_as_float(bits);
    if (cmax > d_hmap[i]) {
        d_hmap[i] = cmax;
        d_obs[i]  = 1;
        int pix = (int)(~(unsigned int)(pb & 0xFFFFFFFFull));
        int pos = atomicAdd(&d_count, 1);
        d_list_cell[pos] = i;
        d_list_pix[pos]  = pix;
    }
}

// ---------------- gather winner-pixel features into compact X buffer ----------------
__global__ void gather_x_kernel(const float* __restrict__ features, int t)
{
    int c = threadIdx.x;                         // 64 threads
    int n = d_count;
    for (int pos = blockIdx.x; pos < n; pos += gridDim.x) {
        int pix = d_list_pix[pos];
        d_xc[pos*CFEAT + c] = features[((long)t*CFEAT + c)*PPIX + pix];
    }
}

// ---------------- fused GRU GEMM: 64 rows x 64 cols per block, f32x2 packed FMA ----------------
#define GRU_INNER(G0)                                                                  \
    _Pragma("unroll")                                                                  \
    for (int kk = 0; kk < 32; ++kk) {                                                  \
        float4 a4 = *reinterpret_cast<const float4*>(&sA[kk*AP + rb]);                 \
        unsigned long long ap0, ap1, ap2, ap3;                                         \
        asm("mov.b64 %0,{%1,%1};" : "=l"(ap0) : "f"(a4.x));                            \
        asm("mov.b64 %0,{%1,%1};" : "=l"(ap1) : "f"(a4.y));                            \
        asm("mov.b64 %0,{%1,%1};" : "=l"(ap2) : "f"(a4.z));                            \
        asm("mov.b64 %0,{%1,%1};" : "=l"(ap3) : "f"(a4.w));                            \
        _Pragma("unroll")                                                              \
        for (int g = 0; g < 3; ++g) {                                                  \
            float4 w4 = *reinterpret_cast<const float4*>(&sW[g][kk*AP + cb]);          \
            unsigned long long wp0, wp1;                                               \
            asm("mov.b64 %0,{%1,%2};" : "=l"(wp0) : "f"(w4.x), "f"(w4.y));             \
            asm("mov.b64 %0,{%1,%2};" : "=l"(wp1) : "f"(w4.z), "f"(w4.w));             \
            asm("fma.rn.f32x2 %0, %1, %2, %0;" : "+l"(acc[G0+g][0][0]) : "l"(ap0), "l"(wp0)); \
            asm("fma.rn.f32x2 %0, %1, %2, %0;" : "+l"(acc[G0+g][0][1]) : "l"(ap0), "l"(wp1)); \
            asm("fma.rn.f32x2 %0, %1, %2, %0;" : "+l"(acc[G0+g][1][0]) : "l"(ap1), "l"(wp0)); \
            asm("fma.rn.f32x2 %0, %1, %2, %0;" : "+l"(acc[G0+g][1][1]) : "l"(ap1), "l"(wp1)); \
            asm("fma.rn.f32x2 %0, %1, %2, %0;" : "+l"(acc[G0+g][2][0]) : "l"(ap2), "l"(wp0)); \
            asm("fma.rn.f32x2 %0, %1, %2, %0;" : "+l"(acc[G0+g][2][1]) : "l"(ap2), "l"(wp1)); \
            asm("fma.rn.f32x2 %0, %1, %2, %0;" : "+l"(acc[G0+g][3][0]) : "l"(ap3), "l"(wp0)); \
            asm("fma.rn.f32x2 %0, %1, %2, %0;" : "+l"(acc[G0+g][3][1]) : "l"(ap3), "l"(wp1)); \
        }                                                                              \
    }

__global__ __launch_bounds__(256) void gru_kernel(const float* __restrict__ Wih,
                                                  const float* __restrict__ Whh,
                                                  const float* __restrict__ bih,
                                                  const float* __restrict__ bhh)
{
    __shared__ float sA[32*AP];
    __shared__ float sW[3][32*AP];
    __shared__ int   sCell[64];

    int n = d_count;
    int row0 = blockIdx.x * 64;
    if (row0 >= n) return;
    int m0 = blockIdx.y * 64;

    int tid = threadIdx.x;
    int tx = tid & 15, ty = tid >> 4;
    int rb = ty * 4, cb = tx * 4;

    if (tid < 64) {
        int rr = min(row0 + tid, n - 1);
        sCell[tid] = d_list_cell[rr];
    }
    __syncthreads();

    // acc[gate 0..2 = x-part | 3..5 = h-part][row 0..3][colpair 0..1], packed f32x2
    unsigned long long acc[6][4][2];
#pragma unroll
    for (int g = 0; g < 6; ++g)
#pragma unroll
        for (int r = 0; r < 4; ++r) { acc[g][r][0] = 0ull; acc[g][r][1] = 0ull; }

    // ---- phase X: K = 64 over compact features ----
    for (int k0 = 0; k0 < CFEAT; k0 += 32) {
        for (int e = tid; e < 64*32; e += 256) {
            int r = e >> 5, kk = e & 31;
            int rr = min(row0 + r, n - 1);
            sA[kk*AP + r] = d_xc[rr*CFEAT + k0 + kk];
        }
        for (int e = tid; e < 3*64*32; e += 256) {
            int g = e >> 11, rem = e & 2047;
            int j = rem >> 5, kk = rem & 31;
            sW[g][kk*AP + j] = Wih[(g*256 + m0 + j)*CFEAT + k0 + kk];
        }
        __syncthreads();
        GRU_INNER(0)
        __syncthreads();
    }

    // ---- phase H: K = 256 over previous state ----
    for (int k0 = 0; k0 < MEMN; k0 += 32) {
        for (int e = tid; e < 64*32; e += 256) {
            int r = e >> 5, kk = e & 31;
            sA[kk*AP + r] = d_state[(long)sCell[r]*MEMN + k0 + kk];
        }
        for (int e = tid; e < 3*64*32; e += 256) {
            int g = e >> 11, rem = e & 2047;
            int j = rem >> 5, kk = rem & 31;
            sW[g][kk*AP + j] = Whh[(g*256 + m0 + j)*MEMN + k0 + kk];
        }
        __syncthreads();
        GRU_INNER(3)
        __syncthreads();
    }

    // ---- epilogue: biases + GRU gates + write new state to compact tmp buffer ----
    float bir[4], biz[4], bin_[4], bhr[4], bhz[4], bhn[4];
    {
        float4 v;
        v = *reinterpret_cast<const float4*>(&bih[      m0 + cb]); bir[0]=v.x; bir[1]=v.y; bir[2]=v.z; bir[3]=v.w;
        v = *reinterpret_cast<const float4*>(&bih[256 + m0 + cb]); biz[0]=v.x; biz[1]=v.y; biz[2]=v.z; biz[3]=v.w;
        v = *reinterpret_cast<const float4*>(&bih[512 + m0 + cb]); bin_[0]=v.x; bin_[1]=v.y; bin_[2]=v.z; bin_[3]=v.w;
        v = *reinterpret_cast<const float4*>(&bhh[      m0 + cb]); bhr[0]=v.x; bhr[1]=v.y; bhr[2]=v.z; bhr[3]=v.w;
        v = *reinterpret_cast<const float4*>(&bhh[256 + m0 + cb]); bhz[0]=v.x; bhz[1]=v.y; bhz[2]=v.z; bhz[3]=v.w;
        v = *reinterpret_cast<const float4*>(&bhh[512 + m0 + cb]); bhn[0]=v.x; bhn[1]=v.y; bhn[2]=v.z; bhn[3]=v.w;
    }

#pragma unroll
    for (int r = 0; r < 4; ++r) {
        int pos = row0 + rb + r;
        bool valid = pos < n;
        int cell = sCell[rb + r];
        float4 h4 = *reinterpret_cast<const float4*>(&d_state[(long)cell*MEMN + m0 + cb]);
        float ho[4] = {h4.x, h4.y, h4.z, h4.w};
        float hnew[4];
#pragma unroll
        for (int cc = 0; cc < 4; ++cc) {
            int cp = cc >> 1;
            float ir  = (cc & 1) ? hi32(acc[0][r][cp]) : lo32(acc[0][r][cp]);
            float iz  = (cc & 1) ? hi32(acc[1][r][cp]) : lo32(acc[1][r][cp]);
            float in_ = (cc & 1) ? hi32(acc[2][r][cp]) : lo32(acc[2][r][cp]);
            float hr  = (cc & 1) ? hi32(acc[3][r][cp]) : lo32(acc[3][r][cp]);
            float hz  = (cc & 1) ? hi32(acc[4][r][cp]) : lo32(acc[4][r][cp]);
            float hn  = (cc & 1) ? hi32(acc[5][r][cp]) : lo32(acc[5][r][cp]);
            ir += bir[cc]; iz += biz[cc]; in_ += bin_[cc];
            hr += bhr[cc]; hz += bhz[cc]; hn += bhn[cc];
            float rg = 1.f / (1.f + expf(-(ir + hr)));
            float zg = 1.f / (1.f + expf(-(iz + hz)));
            float ng = tanhf(in_ + rg * hn);
            hnew[cc] = (1.f - zg) * ng + zg * ho[cc];
        }
        if (valid) {
            float4 o; o.x = hnew[0]; o.y = hnew[1]; o.z = hnew[2]; o.w = hnew[3];
            *reinterpret_cast<float4*>(&d_tmph[(long)pos*MEMN + m0 + cb]) = o;
        }
    }
}

// ---------------- scatter new states back into the map ----------------
__global__ void scatter_h_kernel()
{
    int n = d_count;
    for (int pos = blockIdx.x; pos < n; pos += gridDim.x) {
        int cell = d_list_cell[pos];
        d_state[(long)cell*MEMN + threadIdx.x] = d_tmph[(long)pos*MEMN + threadIdx.x];
    }
}

// ---------------- outputs ----------------
__global__ void transpose_out_kernel(float* __restrict__ out, long out_size)
{
    __shared__ float tile[32][33];
    int c0 = blockIdx.x * 32;   // cell
    int m0 = blockIdx.y * 32;   // mem channel
    int tx = threadIdx.x, ty = threadIdx.y;
#pragma unroll
    for (int i = 0; i < 32; i += 8)
        tile[ty + i][tx] = d_state[(long)(c0 + ty + i)*MEMN + m0 + tx];
    __syncthreads();
#pragma unroll
    for (int i = 0; i < 32; i += 8) {
        long o = (long)(m0 + ty + i)*HWCELLS + c0 + tx;
        if (o < out_size) out[o] = tile[tx][ty + i];
    }
}

__global__ void tail_out_kernel(float* __restrict__ out, long out_size)
{
    int i = blockIdx.x * blockDim.x + threadIdx.x;
    if (i >= HWCELLS) return;
    long o1 = (long)MEMN*HWCELLS + i;
    long o2 = o1 + HWCELLS;
    if (o1 < out_size) out[o1] = d_obs[i] ? 1.f : 0.f;
    if (o2 < out_size) out[o2] = d_hmap[i];
}

// ---------------- launch ----------------
extern "C" void kernel_launch(void* const* d_in, const int* in_sizes, int n_in,
                              void* d_out, int out_size)
{
    // Resolve inputs by element count (robust to scalar inputs present or absent).
    const float* features = nullptr;
    const int*   wtm      = nullptr;
    const void*  mask     = nullptr;
    const float* heights  = nullptr;
    const float* Wih = nullptr; const float* Whh = nullptr;
    const float* bih = nullptr; const float* bhh = nullptr;

    for (int i = 0; i < n_in; ++i) {
        int s = in_sizes[i];
        if      (s == TFRAMES*CFEAT*PPIX) features = (const float*)d_in[i];
        else if (s == TFRAMES*PPIX*2)     wtm      = (const int*)d_in[i];
        else if (s == TFRAMES*PPIX)       { if (!mask) mask = d_in[i]; else heights = (const float*)d_in[i]; }
        else if (s == G3*CFEAT)           Wih = (const float*)d_in[i];
        else if (s == G3*MEMN)            Whh = (const float*)d_in[i];
        else if (s == G3)                 { if (!bih) bih = (const float*)d_in[i]; else bhh = (const float*)d_in[i]; }
    }
    float* out = (float*)d_out;

    detect_mask_kernel<<<1, 1>>>((const unsigned char*)mask);
    init_all_kernel<<<2048, 256>>>();

    for (int t = 0; t < TFRAMES; ++t) {
        frame_reset_kernel<<<(HWCELLS + 255)/256, 256>>>();
        scatter_kernel<<<(PPIX + 255)/256, 256>>>(mask, wtm, heights, t);
        cell_kernel<<<HWCELLS/256, 256>>>();
        gather_x_kernel<<<8192, 64>>>(features, t);
        gru_kernel<<<dim3(HWCELLS/64, 4), 256>>>(Wih, Whh, bih, bhh);
        scatter_h_kernel<<<8192, 256>>>();
    }

    transpose_out_kernel<<<dim3(HWCELLS/32, MEMN/32), dim3(32, 8)>>>(out, (long)out_size);
    tail_out_kernel<<<HWCELLS/256, 256>>>(out, (long)out_size);
}